// round 5
// baseline (speedup 1.0000x reference)
#include <cuda_runtime.h>
#include <cstdint>
#include <math.h>

#define LL   12
#define BB   4
#define CC   768
#define HHH  16
#define WWW  16
#define NN   30000
#define DD   128
#define PEK  192
#define HWK  256
#define NPB  64
#define NBLK_SEL 469               // ceil(30000/64)

#define NCELL 289                  // 17*17 bilinear cells
#define CHUNK 64
#define NCHUNK_MAX (NCELL + (NN + CHUNK - 1) / CHUNK)   // 758

// selector shared strides (conflict-free mma fragment access)
#define PE_S 196
#define H_S  132
#define W_S  136

#define SEL_SMEM_FLOATS (NPB*PE_S + NPB*H_S + 2*64*W_S + NPB*12 + NPB + NPB)
#define SEL_SMEM_BYTES  (SEL_SMEM_FLOATS * 4)

// final2 smem: feat[12][4][4][128] + gb[12][4][128] + wL[64][48] + wG[64][12] + nidx[64]
#define FIN_SMEM_BYTES (98304 + 24576 + 12288 + 3072 + 256)

// ---------------- scratch ----------------
__device__ float g_cwT [LL*CC*DD];
__device__ float g_feat[LL*HWK*BB*DD];    // [l][site][b][d]
__device__ float g_gb  [LL*BB*DD];
__device__ float g_selL[NN*LL];
__device__ float g_px  [NN];
__device__ float g_py  [NN];
__device__ float g_ss  [NN];
__device__ float g_part[2*NBLK_SEL];
// binning
__device__ int g_key [NN];
__device__ int g_perm[NN];
__device__ int g_hist[NCELL];
__device__ int g_cur [NCELL];
__device__ int g_chunk_cell[NCHUNK_MAX];
__device__ int g_chunk_base[NCHUNK_MAX];
__device__ int g_chunk_cnt [NCHUNK_MAX];
__device__ int g_nchunks;

__device__ __forceinline__ float gelu_exact(float x) {
    return 0.5f * x * (1.0f + erff(x * 0.7071067811865476f));
}

__device__ __forceinline__ unsigned int to_tf32(float x) {
    unsigned int u;
    asm("cvt.rna.tf32.f32 %0, %1;" : "=r"(u) : "f"(x));
    return u;
}

__device__ __forceinline__ void mma_tf32(float c[4], unsigned int a0, unsigned int a1,
                                         unsigned int a2, unsigned int a3,
                                         unsigned int b0, unsigned int b1) {
    asm volatile(
        "mma.sync.aligned.m16n8k8.row.col.f32.tf32.tf32.f32 "
        "{%0,%1,%2,%3},{%4,%5,%6,%7},{%8,%9},{%0,%1,%2,%3};\n"
        : "+f"(c[0]), "+f"(c[1]), "+f"(c[2]), "+f"(c[3])
        : "r"(a0), "r"(a1), "r"(a2), "r"(a3), "r"(b0), "r"(b1));
}

// ---------------- conv_w transpose ----------------
__global__ void transpose_cw_kernel(const float* __restrict__ cw) {
    __shared__ float t[32][33];
    const int l  = blockIdx.z;
    const int d0 = blockIdx.x * 32;
    const int c0 = blockIdx.y * 32;
    for (int i = threadIdx.y; i < 32; i += 8)
        t[i][threadIdx.x] = cw[((size_t)l*DD + d0 + i)*CC + c0 + threadIdx.x];
    __syncthreads();
    for (int i = threadIdx.y; i < 32; i += 8)
        g_cwT[((size_t)l*CC + c0 + i)*DD + d0 + threadIdx.x] = t[threadIdx.x][i];
}

// ---------------- selector v3: 3xTF32 tensor-core MLP ----------------
__device__ __forceinline__ void gemm_layer_3xtf32(
    const float* __restrict__ A, int As, int K,
    const float* __restrict__ Wg,
    float* wh_s, float* wl_s, float cacc[8][4],
    int tid, int nw, int jw, int r, int c)
{
    for (int kc = 0; kc < K; kc += 64) {
        __syncthreads();
        for (int i = tid; i < 64*32; i += 256) {
            int row = i >> 5, c4 = (i & 31) * 4;
            float4 v = *(const float4*)(Wg + (size_t)(kc + row)*DD + c4);
            uint4 hi, lo;
            hi.x = to_tf32(v.x); lo.x = to_tf32(v.x - __uint_as_float(hi.x));
            hi.y = to_tf32(v.y); lo.y = to_tf32(v.y - __uint_as_float(hi.y));
            hi.z = to_tf32(v.z); lo.z = to_tf32(v.z - __uint_as_float(hi.z));
            hi.w = to_tf32(v.w); lo.w = to_tf32(v.w - __uint_as_float(hi.w));
            *(uint4*)&wh_s[row*W_S + c4] = hi;
            *(uint4*)&wl_s[row*W_S + c4] = lo;
        }
        __syncthreads();
        #pragma unroll
        for (int ks = 0; ks < 8; ks++) {
            int kk = ks * 8;
            float a0f = A[(nw + r    )*As + kc + kk + c    ];
            float a1f = A[(nw + r + 8)*As + kc + kk + c    ];
            float a2f = A[(nw + r    )*As + kc + kk + c + 4];
            float a3f = A[(nw + r + 8)*As + kc + kk + c + 4];
            unsigned int ah0 = to_tf32(a0f), ah1 = to_tf32(a1f);
            unsigned int ah2 = to_tf32(a2f), ah3 = to_tf32(a3f);
            unsigned int al0 = to_tf32(a0f - __uint_as_float(ah0));
            unsigned int al1 = to_tf32(a1f - __uint_as_float(ah1));
            unsigned int al2 = to_tf32(a2f - __uint_as_float(ah2));
            unsigned int al3 = to_tf32(a3f - __uint_as_float(ah3));
            #pragma unroll
            for (int jt = 0; jt < 8; jt++) {
                unsigned int bh0 = __float_as_uint(wh_s[(kk + c    )*W_S + jw + jt*8 + r]);
                unsigned int bh1 = __float_as_uint(wh_s[(kk + c + 4)*W_S + jw + jt*8 + r]);
                unsigned int bl0 = __float_as_uint(wl_s[(kk + c    )*W_S + jw + jt*8 + r]);
                unsigned int bl1 = __float_as_uint(wl_s[(kk + c + 4)*W_S + jw + jt*8 + r]);
                mma_tf32(cacc[jt], ah0, ah1, ah2, ah3, bh0, bh1);
                mma_tf32(cacc[jt], al0, al1, al2, al3, bh0, bh1);
                mma_tf32(cacc[jt], ah0, ah1, ah2, ah3, bl0, bl1);
            }
        }
    }
}

__global__ __launch_bounds__(256) void selector2_kernel(
    const float* __restrict__ coords,
    const float* __restrict__ W1all, const float* __restrict__ b1all,
    const float* __restrict__ W2all, const float* __restrict__ b2all,
    const float* __restrict__ W3s,   const float* __restrict__ W3l,
    const float* __restrict__ W3c)
{
    extern __shared__ float smem[];
    float* pe_s  = smem;                      // [64][PE_S] fp32
    float* h_s   = pe_s + NPB*PE_S;           // [64][H_S]  fp32
    float* wh_s  = h_s  + NPB*H_S;            // [64][W_S]  tf32 hi
    float* wl_s  = wh_s + 64*W_S;             // [64][W_S]  tf32 lo
    float* outs  = wl_s + 64*W_S;             // [64][12]
    float* ent_s = outs + NPB*12;
    float* sq_s  = ent_s + NPB;

    const int tid  = threadIdx.x;
    const int n0   = blockIdx.x * NPB;
    const int wid  = tid >> 5;
    const int lane = tid & 31;
    const int r    = lane >> 2;
    const int c    = lane & 3;
    const int nw   = (wid >> 1) * 16;
    const int jw   = (wid & 1) * 64;

    for (int idx = tid; idx < NPB*PEK; idx += 256) {
        int n = idx / PEK, k = idx - n*PEK;
        int cc = k >> 6, rr = k & 63, f = rr & 31;
        int gn = n0 + n;
        float x = (gn < NN) ? coords[gn*3 + cc] : 0.0f;
        float freq = exp2f((8.0f/31.0f) * (float)f) * 3.14159265358979323846f;
        float ang = x * freq;
        pe_s[n*PE_S + k] = (rr < 32) ? sinf(ang) : cosf(ang);
    }
    __syncthreads();

    for (int head = 0; head < 3; head++) {
        const float* w1 = W1all + (size_t)head*PEK*DD;
        const float* w2 = W2all + (size_t)head*DD*DD;
        float cacc[8][4];

        #pragma unroll
        for (int jt = 0; jt < 8; jt++)
            #pragma unroll
            for (int i = 0; i < 4; i++) cacc[jt][i] = 0.0f;
        gemm_layer_3xtf32(pe_s, PE_S, PEK, w1, wh_s, wl_s, cacc, tid, nw, jw, r, c);
        #pragma unroll
        for (int jt = 0; jt < 8; jt++) {
            int col = jw + jt*8 + 2*c;
            float bz0 = b1all[head*DD + col], bz1 = b1all[head*DD + col + 1];
            h_s[(nw + r    )*H_S + col    ] = gelu_exact(cacc[jt][0] + bz0);
            h_s[(nw + r    )*H_S + col + 1] = gelu_exact(cacc[jt][1] + bz1);
            h_s[(nw + r + 8)*H_S + col    ] = gelu_exact(cacc[jt][2] + bz0);
            h_s[(nw + r + 8)*H_S + col + 1] = gelu_exact(cacc[jt][3] + bz1);
        }
        #pragma unroll
        for (int jt = 0; jt < 8; jt++)
            #pragma unroll
            for (int i = 0; i < 4; i++) cacc[jt][i] = 0.0f;
        gemm_layer_3xtf32(h_s, H_S, DD, w2, wh_s, wl_s, cacc, tid, nw, jw, r, c);
        __syncthreads();
        #pragma unroll
        for (int jt = 0; jt < 8; jt++) {
            int col = jw + jt*8 + 2*c;
            float bz0 = b2all[head*DD + col], bz1 = b2all[head*DD + col + 1];
            h_s[(nw + r    )*H_S + col    ] = gelu_exact(cacc[jt][0] + bz0);
            h_s[(nw + r    )*H_S + col + 1] = gelu_exact(cacc[jt][1] + bz1);
            h_s[(nw + r + 8)*H_S + col    ] = gelu_exact(cacc[jt][2] + bz0);
            h_s[(nw + r + 8)*H_S + col + 1] = gelu_exact(cacc[jt][3] + bz1);
        }
        __syncthreads();

        if (head == 0) {
            if (tid < 128) {
                int n = tid >> 1, j = tid & 1;
                float a = 0.0f;
                for (int k = 0; k < DD; k++) a += h_s[n*H_S + k] * W3s[k*2 + j];
                outs[n*12 + j] = tanhf(a);
            }
            __syncthreads();
            if (tid < NPB) {
                int gn = n0 + tid;
                if (gn < NN) {
                    g_px[gn] = (outs[tid*12 + 0] + 1.0f) * (WWW * 0.5f) - 0.5f;
                    g_py[gn] = (outs[tid*12 + 1] + 1.0f) * (HHH * 0.5f) - 0.5f;
                }
            }
            __syncthreads();
        } else if (head == 1) {
            for (int idx = tid; idx < NPB*12; idx += 256) {
                int n = idx / 12, j = idx - n*12;
                float a = 0.0f;
                for (int k = 0; k < DD; k++) a += h_s[n*H_S + k] * W3l[k*12 + j];
                outs[n*12 + j] = a;
            }
            __syncthreads();
            if (tid < NPB) {
                int gn = n0 + tid;
                float m = outs[tid*12];
                #pragma unroll
                for (int l = 1; l < 12; l++) m = fmaxf(m, outs[tid*12 + l]);
                float s = 0.0f, e[12];
                #pragma unroll
                for (int l = 0; l < 12; l++) { e[l] = expf(outs[tid*12 + l] - m); s += e[l]; }
                float inv = 1.0f / s;
                float en = 0.0f;
                #pragma unroll
                for (int l = 0; l < 12; l++) {
                    float p = e[l] * inv;
                    if (gn < NN) g_selL[(size_t)gn*12 + l] = p;
                    en += p * logf(p + 1e-8f);
                }
                ent_s[tid] = (gn < NN) ? en : 0.0f;
            }
            __syncthreads();
        } else {
            if (tid < NPB) {
                int gn = n0 + tid;
                float a = 0.0f;
                for (int k = 0; k < DD; k++) a += h_s[tid*H_S + k] * W3c[k];
                float s = 1.0f / (1.0f + expf(-a));
                if (gn < NN) g_ss[gn] = s;
                sq_s[tid] = (gn < NN) ? (s - 0.5f) * (s - 0.5f) : 0.0f;
            }
            __syncthreads();
        }
    }

    if (tid == 0) {
        float es = 0.0f, qs = 0.0f;
        for (int i = 0; i < NPB; i++) { es += ent_s[i]; qs += sq_s[i]; }
        g_part[blockIdx.x*2 + 0] = es;
        g_part[blockIdx.x*2 + 1] = qs;
    }
}

// ---------------- feat GEMM ----------------
__global__ __launch_bounds__(256) void feat_kernel(const float* __restrict__ lt) {
    __shared__ float a_s[8][36];
    __shared__ float w_s[8][128];
    const int lb  = blockIdx.y;
    const int l   = lb >> 2;
    const int hw0 = blockIdx.x * 32;
    const int tid = threadIdx.x;
    const int td  = tid & 31;
    const int thw = tid >> 5;
    const int b   = lb & 3;

    float acc[4][4];
    #pragma unroll
    for (int i = 0; i < 4; i++)
        #pragma unroll
        for (int j = 0; j < 4; j++) acc[i][j] = 0.0f;

    const float* base = lt + (size_t)lb * CC * HWK;

    for (int c0 = 0; c0 < CC; c0 += 8) {
        {
            int kk = tid >> 5, s = tid & 31;
            a_s[kk][s] = base[(size_t)(c0+kk)*HWK + hw0 + s];
            *(float4*)&w_s[kk][s*4] =
                *(const float4*)&g_cwT[((size_t)l*CC + c0 + kk)*DD + s*4];
        }
        __syncthreads();
        #pragma unroll
        for (int kk = 0; kk < 8; kk++) {
            float4 w = *(float4*)&w_s[kk][td*4];
            #pragma unroll
            for (int i = 0; i < 4; i++) {
                float p = a_s[kk][thw*4 + i];
                acc[i][0] += p*w.x; acc[i][1] += p*w.y;
                acc[i][2] += p*w.z; acc[i][3] += p*w.w;
            }
        }
        __syncthreads();
    }
    #pragma unroll
    for (int i = 0; i < 4; i++) {
        int site = hw0 + thw*4 + i;
        float4 v = make_float4(acc[i][0], acc[i][1], acc[i][2], acc[i][3]);
        *(float4*)&g_feat[(((size_t)l*HWK + site)*BB + b)*DD + td*4] = v;
    }
}

// ---------------- global bottleneck ----------------
__global__ __launch_bounds__(256) void gb_kernel(const float* __restrict__ gt,
                                                 const float* __restrict__ gw) {
    int wid  = (blockIdx.x * 256 + threadIdx.x) >> 5;
    int lane = threadIdx.x & 31;
    if (wid >= LL*BB*DD) return;
    int l = wid / (BB*DD);
    int rr = wid - l*(BB*DD);
    int b = rr / DD;
    int d = rr - b*DD;
    const float* a = gt + (size_t)(l*BB + b)*CC;
    const float* w = gw + (size_t)(l*DD + d)*CC;
    float s = 0.0f;
    for (int cc = lane; cc < CC; cc += 32) s += a[cc] * w[cc];
    #pragma unroll
    for (int o = 16; o; o >>= 1) s += __shfl_xor_sync(0xffffffffu, s, o);
    if (lane == 0) g_gb[(size_t)(l*BB + b)*DD + d] = s;
}

// ---------------- binning ----------------
__global__ void init_hist_kernel() {
    int t = blockIdx.x * 256 + threadIdx.x;
    if (t < NCELL) g_hist[t] = 0;
}

__global__ void key_kernel() {
    int n = blockIdx.x * 256 + threadIdx.x;
    if (n >= NN) return;
    int x0 = (int)floorf(g_px[n]);   // in [-1, 15] (tanh bounds)
    int y0 = (int)floorf(g_py[n]);
    x0 = min(max(x0, -1), 15);
    y0 = min(max(y0, -1), 15);
    int key = (y0 + 1) * 17 + (x0 + 1);
    g_key[n] = key;
    atomicAdd(&g_hist[key], 1);
}

__global__ void scan_kernel() {
    if (threadIdx.x != 0 || blockIdx.x != 0) return;
    int off = 0, nch = 0;
    for (int c = 0; c < NCELL; c++) {
        int cnt = g_hist[c];
        g_cur[c] = off;
        for (int base = 0; base < cnt; base += CHUNK) {
            g_chunk_cell[nch] = c;
            g_chunk_base[nch] = off + base;
            g_chunk_cnt [nch] = min(CHUNK, cnt - base);
            nch++;
        }
        off += cnt;
    }
    g_nchunks = nch;
}

__global__ void scatter_kernel() {
    int n = blockIdx.x * 256 + threadIdx.x;
    if (n >= NN) return;
    int pos = atomicAdd(&g_cur[g_key[n]], 1);
    g_perm[pos] = n;
}

// ---------------- final v2: cell-binned gather ----------------
__global__ __launch_bounds__(512) void final2_kernel(const float* __restrict__ ow,
                                                     const float* __restrict__ ob,
                                                     float* __restrict__ out) {
    extern __shared__ float s[];
    float* feat_s = s;                        // [12][4][4][128] = 24576 floats
    float* gb_s   = feat_s + 24576;           // [12][4][128]    = 6144
    float* wL_s   = gb_s + 6144;              // [64][48]
    float* wG_s   = wL_s + 64*48;             // [64][12]
    int*   nidx   = (int*)(wG_s + 64*12);     // [64]

    const int bid = blockIdx.x;
    if (bid >= g_nchunks) return;
    const int tid  = threadIdx.x;
    const int cell = g_chunk_cell[bid];
    const int base = g_chunk_base[bid];
    const int cnt  = g_chunk_cnt [bid];

    const int ky = cell / 17 - 1;   // y0
    const int kx = cell % 17 - 1;   // x0
    const bool vx0 = (kx >= 0),  vx1 = (kx + 1 <= 15);
    const bool vy0 = (ky >= 0),  vy1 = (ky + 1 <= 15);
    const int sx0 = min(max(kx,     0), 15), sx1 = min(max(kx + 1, 0), 15);
    const int sy0 = min(max(ky,     0), 15), sy1 = min(max(ky + 1, 0), 15);
    int site[4];
    site[0] = sy0*16 + sx0; site[1] = sy0*16 + sx1;
    site[2] = sy1*16 + sx0; site[3] = sy1*16 + sx1;

    // load feat tile: 6144 float4
    {
        const float4* gf = (const float4*)g_feat;
        float4* fs = (float4*)feat_s;
        #pragma unroll
        for (int it = 0; it < 12; it++) {
            int i = tid + it*512;
            int l  = i >> 9;
            int rm = i & 511;
            int p  = rm >> 7;
            int b  = (rm >> 5) & 3;
            int d4 = rm & 31;
            fs[i] = gf[((l*HWK + site[p])*BB + b)*32 + d4];
        }
        const float4* gg = (const float4*)g_gb;
        float4* gs = (float4*)gb_s;
        #pragma unroll
        for (int it = 0; it < 3; it++)
            gs[tid + it*512] = gg[tid + it*512];
    }

    // per-point weights
    if (tid < CHUNK) {
        int n = (tid < cnt) ? g_perm[base + tid] : -1;
        nidx[tid] = n;
        if (n >= 0) {
            float px = g_px[n], py = g_py[n], ss = g_ss[n];
            float wx1 = px - (float)kx, wy1 = py - (float)ky;
            float wx0 = 1.0f - wx1, wy0 = 1.0f - wy1;
            float cw[4];
            cw[0] = (vx0 && vy0) ? wx0*wy0 : 0.0f;
            cw[1] = (vx1 && vy0) ? wx1*wy0 : 0.0f;
            cw[2] = (vx0 && vy1) ? wx0*wy1 : 0.0f;
            cw[3] = (vx1 && vy1) ? wx1*wy1 : 0.0f;
            float oms = 1.0f - ss;
            #pragma unroll
            for (int l = 0; l < LL; l++) {
                float wl = g_selL[(size_t)n*12 + l];
                float owl = oms * wl;
                wL_s[tid*48 + l*4 + 0] = owl * cw[0];
                wL_s[tid*48 + l*4 + 1] = owl * cw[1];
                wL_s[tid*48 + l*4 + 2] = owl * cw[2];
                wL_s[tid*48 + l*4 + 3] = owl * cw[3];
                wG_s[tid*12 + l] = ss * wl;
            }
        } else {
            #pragma unroll
            for (int l = 0; l < LL; l++) {
                wL_s[tid*48 + l*4 + 0] = 0.0f; wL_s[tid*48 + l*4 + 1] = 0.0f;
                wL_s[tid*48 + l*4 + 2] = 0.0f; wL_s[tid*48 + l*4 + 3] = 0.0f;
                wG_s[tid*12 + l] = 0.0f;
            }
        }
    }
    __syncthreads();

    // compute: warp = (pg, b); 16 points per warp
    const int wid  = tid >> 5;
    const int lane = tid & 31;
    const int b    = wid & 3;
    const int pg   = wid >> 2;      // 0..3
    const float4* fs = (const float4*)feat_s;
    const float4* gs = (const float4*)gb_s;
    const float*  wLp = wL_s + (pg*16)*48;
    const float*  wGp = wG_s + (pg*16)*12;

    float4 acc[16];
    #pragma unroll
    for (int k = 0; k < 16; k++) acc[k] = make_float4(0,0,0,0);

    for (int l = 0; l < LL; l++) {
        #pragma unroll
        for (int p = 0; p < 4; p++) {
            float4 f = fs[(l*16 + p*4 + b)*32 + lane];
            #pragma unroll
            for (int k = 0; k < 16; k++) {
                float w = wLp[k*48 + l*4 + p];
                acc[k].x += w*f.x; acc[k].y += w*f.y;
                acc[k].z += w*f.z; acc[k].w += w*f.w;
            }
        }
        float4 g = gs[(l*4 + b)*32 + lane];
        #pragma unroll
        for (int k = 0; k < 16; k++) {
            float w = wGp[k*12 + l];
            acc[k].x += w*g.x; acc[k].y += w*g.y;
            acc[k].z += w*g.z; acc[k].w += w*g.w;
        }
    }

    #pragma unroll
    for (int k = 0; k < 16; k++) {
        int n = nidx[pg*16 + k];
        if (n < 0) continue;
        float4 o4 = *(const float4*)&ow[(size_t)n*DD + lane*4];
        float dot = acc[k].x*o4.x + acc[k].y*o4.y + acc[k].z*o4.z + acc[k].w*o4.w;
        #pragma unroll
        for (int o = 16; o; o >>= 1) dot += __shfl_xor_sync(0xffffffffu, dot, o);
        if (lane == 0) out[b*NN + n] = dot * (1.0f/DD) + ob[n];
    }
}

// ---------------- reg scalar ----------------
__global__ void reg_kernel(float* __restrict__ out, int has_reg) {
    if (threadIdx.x == 0 && blockIdx.x == 0) {
        float es = 0.0f, qs = 0.0f;
        for (int i = 0; i < NBLK_SEL; i++) { es += g_part[2*i]; qs += g_part[2*i+1]; }
        float entropy = es / (float)NN;
        float reg = entropy / logf(12.0f) + qs / (float)NN;
        if (has_reg) out[BB*NN] = reg;
    }
}

// ---------------- launch ----------------
extern "C" void kernel_launch(void* const* d_in, const int* in_sizes, int n_in,
                              void* d_out, int out_size) {
    const float* lt     = (const float*)d_in[0];
    const float* gt     = (const float*)d_in[1];
    const float* coords = (const float*)d_in[2];
    const float* conv_w = (const float*)d_in[3];
    const float* glob_w = (const float*)d_in[4];
    const float* W1     = (const float*)d_in[5];
    const float* b1     = (const float*)d_in[6];
    const float* W2     = (const float*)d_in[7];
    const float* b2     = (const float*)d_in[8];
    const float* W3s    = (const float*)d_in[9];
    const float* W3l    = (const float*)d_in[10];
    const float* W3c    = (const float*)d_in[11];
    const float* ow     = (const float*)d_in[12];
    const float* ob     = (const float*)d_in[13];
    float* out = (float*)d_out;

    cudaFuncSetAttribute(selector2_kernel,
                         cudaFuncAttributeMaxDynamicSharedMemorySize, SEL_SMEM_BYTES);
    cudaFuncSetAttribute(final2_kernel,
                         cudaFuncAttributeMaxDynamicSharedMemorySize, FIN_SMEM_BYTES);

    transpose_cw_kernel<<<dim3(4, 24, 12), dim3(32, 8)>>>(conv_w);
    selector2_kernel<<<NBLK_SEL, 256, SEL_SMEM_BYTES>>>(coords, W1, b1, W2, b2, W3s, W3l, W3c);
    init_hist_kernel<<<2, 256>>>();
    key_kernel<<<(NN + 255)/256, 256>>>();
    scan_kernel<<<1, 32>>>();
    scatter_kernel<<<(NN + 255)/256, 256>>>();
    feat_kernel<<<dim3(8, 48), 256>>>(lt);
    gb_kernel<<<768, 256>>>(gt, glob_w);
    final2_kernel<<<NCHUNK_MAX, 512, FIN_SMEM_BYTES>>>(ow, ob, out);
    reg_kernel<<<1, 32>>>(out, (out_size > BB*NN) ? 1 : 0);
}

// round 8
// speedup vs baseline: 1.1770x; 1.1770x over previous
#include <cuda_runtime.h>
#include <cuda_bf16.h>
#include <cstdint>
#include <math.h>

#define LL   12
#define BB   4
#define CC   768
#define HHH  16
#define WWW  16
#define NN   30000
#define DD   128
#define PEK  192
#define HWK  256
#define NPB  64
#define NBLK_SEL 469               // ceil(30000/64)

#define NCELL 289                  // 17*17 bilinear cells
#define CHUNK 64
#define NCHUNK_MAX (NCELL + (NN + CHUNK - 1) / CHUNK)   // 758

// packed-pair strides (uint32 words), all ≡ 4 (mod 32) for conflict-free frags
#define PE2S 100                   // 96 pairs + pad
#define H2S  68                    // 64 pairs + pad
#define W2S  132                   // 128 j + pad
#define H32S 132                   // fp32 h2 stride

#define SEL_SMEM_WORDS (2*6400 + 2*4352 + 2*4224 + 8448 + 768 + 128)
#define SEL_SMEM_BYTES (SEL_SMEM_WORDS * 4)     // 157184

#define FIN_SMEM_BYTES (98304 + 24576 + 12288 + 3072 + 256)

// ---------------- scratch ----------------
__device__ float g_cwT [LL*CC*DD];
__device__ float g_feat[LL*HWK*BB*DD];    // [l][site][b][d]
__device__ float g_gb  [LL*BB*DD];
__device__ float g_selL[NN*LL];
__device__ float g_px  [NN];
__device__ float g_py  [NN];
__device__ float g_ss  [NN];
__device__ float g_part[2*NBLK_SEL];
// packed bf16x2 weights (hi/lo split), pair-major [mat][kp][j]
__device__ unsigned int g_w1h[3*96*128];
__device__ unsigned int g_w1l[3*96*128];
__device__ unsigned int g_w2h[3*64*128];
__device__ unsigned int g_w2l[3*64*128];
// binning
__device__ int g_key [NN];
__device__ int g_perm[NN];
__device__ int g_hist[NCELL];
__device__ int g_cur [NCELL];
__device__ int g_chunk_cell[NCHUNK_MAX];
__device__ int g_chunk_base[NCHUNK_MAX];
__device__ int g_chunk_cnt [NCHUNK_MAX];
__device__ int g_nchunks;

__device__ __forceinline__ float gelu_exact(float x) {
    return 0.5f * x * (1.0f + erff(x * 0.7071067811865476f));
}

__device__ __forceinline__ unsigned int pack_hi(float v0, float v1) {
    unsigned short u0 = __bfloat16_as_ushort(__float2bfloat16_rn(v0));
    unsigned short u1 = __bfloat16_as_ushort(__float2bfloat16_rn(v1));
    return (unsigned int)u0 | ((unsigned int)u1 << 16);
}
__device__ __forceinline__ unsigned int pack_lo(float v0, float v1) {
    float h0 = __bfloat162float(__float2bfloat16_rn(v0));
    float h1 = __bfloat162float(__float2bfloat16_rn(v1));
    unsigned short u0 = __bfloat16_as_ushort(__float2bfloat16_rn(v0 - h0));
    unsigned short u1 = __bfloat16_as_ushort(__float2bfloat16_rn(v1 - h1));
    return (unsigned int)u0 | ((unsigned int)u1 << 16);
}

__device__ __forceinline__ void mma_bf16(float c[4],
    unsigned int a0, unsigned int a1, unsigned int a2, unsigned int a3,
    unsigned int b0, unsigned int b1) {
    asm volatile(
        "mma.sync.aligned.m16n8k16.row.col.f32.bf16.bf16.f32 "
        "{%0,%1,%2,%3},{%4,%5,%6,%7},{%8,%9},{%0,%1,%2,%3};\n"
        : "+f"(c[0]), "+f"(c[1]), "+f"(c[2]), "+f"(c[3])
        : "r"(a0), "r"(a1), "r"(a2), "r"(a3), "r"(b0), "r"(b1));
}

// ---------------- weight pack: fp32 [k][j] -> bf16x2 hi/lo [k/2][j] ----------------
__global__ void wpack_kernel(const float* __restrict__ W1all,
                             const float* __restrict__ W2all) {
    int i = blockIdx.x * 256 + threadIdx.x;
    if (i < 3*96*128) {
        int mat = i / (96*128);
        int rem = i - mat*(96*128);
        int kp = rem >> 7, j = rem & 127;
        const float* W = W1all + (size_t)mat*PEK*DD;
        float w0 = W[(2*kp)*DD + j], w1 = W[(2*kp+1)*DD + j];
        g_w1h[i] = pack_hi(w0, w1);
        g_w1l[i] = pack_lo(w0, w1);
    } else if (i < 3*96*128 + 3*64*128) {
        int t = i - 3*96*128;
        int mat = t / (64*128);
        int rem = t - mat*(64*128);
        int kp = rem >> 7, j = rem & 127;
        const float* W = W2all + (size_t)mat*DD*DD;
        float w0 = W[(2*kp)*DD + j], w1 = W[(2*kp+1)*DD + j];
        g_w2h[t] = pack_hi(w0, w1);
        g_w2l[t] = pack_lo(w0, w1);
    }
}

// ---------------- conv_w transpose ----------------
__global__ void transpose_cw_kernel(const float* __restrict__ cw) {
    __shared__ float t[32][33];
    const int l  = blockIdx.z;
    const int d0 = blockIdx.x * 32;
    const int c0 = blockIdx.y * 32;
    for (int i = threadIdx.y; i < 32; i += 8)
        t[i][threadIdx.x] = cw[((size_t)l*DD + d0 + i)*CC + c0 + threadIdx.x];
    __syncthreads();
    for (int i = threadIdx.y; i < 32; i += 8)
        g_cwT[((size_t)l*CC + c0 + i)*DD + d0 + threadIdx.x] = t[threadIdx.x][i];
}

// ---------------- selector v4: 3xBF16 tensor-core MLP ----------------
__device__ __forceinline__ void gemm_layer_3xbf16(
    const unsigned int* Aph, const unsigned int* Apl, int A2S, int KP,
    const unsigned int* __restrict__ Wgh, const unsigned int* __restrict__ Wgl,
    unsigned int* wh_s, unsigned int* wl_s, float cacc[8][4],
    int tid, int nw, int jw, int gid, int tig)
{
    for (int kc2 = 0; kc2 < KP; kc2 += 32) {   // 32 pairs = 64 K per chunk
        __syncthreads();
        for (int i = tid; i < 32*32; i += 256) {
            int row = i >> 5, c4 = (i & 31) * 4;
            *(uint4*)&wh_s[row*W2S + c4] = *(const uint4*)&Wgh[(kc2+row)*128 + c4];
            *(uint4*)&wl_s[row*W2S + c4] = *(const uint4*)&Wgl[(kc2+row)*128 + c4];
        }
        __syncthreads();
        #pragma unroll
        for (int s = 0; s < 4; s++) {          // 4 k16 steps
            int kpA = kc2 + s*8;
            unsigned int ah0 = Aph[(nw+gid  )*A2S + kpA + tig];
            unsigned int ah1 = Aph[(nw+gid+8)*A2S + kpA + tig];
            unsigned int ah2 = Aph[(nw+gid  )*A2S + kpA + tig + 4];
            unsigned int ah3 = Aph[(nw+gid+8)*A2S + kpA + tig + 4];
            unsigned int al0 = Apl[(nw+gid  )*A2S + kpA + tig];
            unsigned int al1 = Apl[(nw+gid+8)*A2S + kpA + tig];
            unsigned int al2 = Apl[(nw+gid  )*A2S + kpA + tig + 4];
            unsigned int al3 = Apl[(nw+gid+8)*A2S + kpA + tig + 4];
            int kps = s*8;
            #pragma unroll
            for (int jt = 0; jt < 8; jt++) {
                int j = jw + jt*8 + gid;
                unsigned int bh0 = wh_s[(kps+tig  )*W2S + j];
                unsigned int bh1 = wh_s[(kps+tig+4)*W2S + j];
                unsigned int bl0 = wl_s[(kps+tig  )*W2S + j];
                unsigned int bl1 = wl_s[(kps+tig+4)*W2S + j];
                mma_bf16(cacc[jt], ah0, ah1, ah2, ah3, bh0, bh1);
                mma_bf16(cacc[jt], al0, al1, al2, al3, bh0, bh1);
                mma_bf16(cacc[jt], ah0, ah1, ah2, ah3, bl0, bl1);
            }
        }
    }
}

__global__ __launch_bounds__(256) void selector3_kernel(
    const float* __restrict__ coords,
    const float* __restrict__ b1all, const float* __restrict__ b2all,
    const float* __restrict__ W3s,   const float* __restrict__ W3l,
    const float* __restrict__ W3c)
{
    extern __shared__ unsigned int smem_u[];
    unsigned int* pe_h = smem_u;                 // [64][PE2S]
    unsigned int* pe_l = pe_h + NPB*PE2S;
    unsigned int* h_ph = pe_l + NPB*PE2S;        // [64][H2S]
    unsigned int* h_pl = h_ph + NPB*H2S;
    unsigned int* wh_s = h_pl + NPB*H2S;         // [32][W2S]
    unsigned int* wl_s = wh_s + 32*W2S;
    float* h32   = (float*)(wl_s + 32*W2S);      // [64][H32S]
    float* outs  = h32 + NPB*H32S;               // [64][12]
    float* ent_s = outs + NPB*12;
    float* sq_s  = ent_s + NPB;

    const int tid  = threadIdx.x;
    const int n0   = blockIdx.x * NPB;
    const int wid  = tid >> 5;
    const int lane = tid & 31;
    const int gid  = lane >> 2;
    const int tig  = lane & 3;
    const int nw   = (wid >> 1) * 16;
    const int jw   = (wid & 1) * 64;

    for (int idx = tid; idx < NPB*96; idx += 256) {
        int n = idx / 96, kp = idx - n*96;
        int gn = n0 + n;
        float v[2];
        #pragma unroll
        for (int e = 0; e < 2; e++) {
            int k = 2*kp + e;
            int cc = k >> 6, rr = k & 63, f = rr & 31;
            float x = (gn < NN) ? coords[gn*3 + cc] : 0.0f;
            float freq = exp2f((8.0f/31.0f) * (float)f) * 3.14159265358979323846f;
            float ang = x * freq;
            v[e] = (rr < 32) ? sinf(ang) : cosf(ang);
        }
        pe_h[n*PE2S + kp] = pack_hi(v[0], v[1]);
        pe_l[n*PE2S + kp] = pack_lo(v[0], v[1]);
    }
    __syncthreads();

    for (int head = 0; head < 3; head++) {
        float cacc[8][4];

        #pragma unroll
        for (int jt = 0; jt < 8; jt++)
            #pragma unroll
            for (int i = 0; i < 4; i++) cacc[jt][i] = 0.0f;
        gemm_layer_3xbf16(pe_h, pe_l, PE2S, 96,
                          g_w1h + head*96*128, g_w1l + head*96*128,
                          wh_s, wl_s, cacc, tid, nw, jw, gid, tig);
        #pragma unroll
        for (int jt = 0; jt < 8; jt++) {
            int col = jw + jt*8 + 2*tig;
            int kp  = col >> 1;
            float bz0 = b1all[head*DD + col], bz1 = b1all[head*DD + col + 1];
            float v0 = gelu_exact(cacc[jt][0] + bz0);
            float v1 = gelu_exact(cacc[jt][1] + bz1);
            float v2 = gelu_exact(cacc[jt][2] + bz0);
            float v3 = gelu_exact(cacc[jt][3] + bz1);
            h_ph[(nw+gid  )*H2S + kp] = pack_hi(v0, v1);
            h_pl[(nw+gid  )*H2S + kp] = pack_lo(v0, v1);
            h_ph[(nw+gid+8)*H2S + kp] = pack_hi(v2, v3);
            h_pl[(nw+gid+8)*H2S + kp] = pack_lo(v2, v3);
        }
        #pragma unroll
        for (int jt = 0; jt < 8; jt++)
            #pragma unroll
            for (int i = 0; i < 4; i++) cacc[jt][i] = 0.0f;
        gemm_layer_3xbf16(h_ph, h_pl, H2S, 64,
                          g_w2h + head*64*128, g_w2l + head*64*128,
                          wh_s, wl_s, cacc, tid, nw, jw, gid, tig);
        __syncthreads();
        #pragma unroll
        for (int jt = 0; jt < 8; jt++) {
            int col = jw + jt*8 + 2*tig;
            float bz0 = b2all[head*DD + col], bz1 = b2all[head*DD + col + 1];
            h32[(nw+gid  )*H32S + col    ] = gelu_exact(cacc[jt][0] + bz0);
            h32[(nw+gid  )*H32S + col + 1] = gelu_exact(cacc[jt][1] + bz1);
            h32[(nw+gid+8)*H32S + col    ] = gelu_exact(cacc[jt][2] + bz0);
            h32[(nw+gid+8)*H32S + col + 1] = gelu_exact(cacc[jt][3] + bz1);
        }
        __syncthreads();

        if (head == 0) {
            if (tid < 128) {
                int n = tid >> 1, j = tid & 1;
                float a = 0.0f;
                for (int k = 0; k < DD; k++) a += h32[n*H32S + k] * W3s[k*2 + j];
                outs[n*12 + j] = tanhf(a);
            }
            __syncthreads();
            if (tid < NPB) {
                int gn = n0 + tid;
                if (gn < NN) {
                    g_px[gn] = (outs[tid*12 + 0] + 1.0f) * (WWW * 0.5f) - 0.5f;
                    g_py[gn] = (outs[tid*12 + 1] + 1.0f) * (HHH * 0.5f) - 0.5f;
                }
            }
            __syncthreads();
        } else if (head == 1) {
            for (int idx = tid; idx < NPB*12; idx += 256) {
                int n = idx / 12, j = idx - n*12;
                float a = 0.0f;
                for (int k = 0; k < DD; k++) a += h32[n*H32S + k] * W3l[k*12 + j];
                outs[n*12 + j] = a;
            }
            __syncthreads();
            if (tid < NPB) {
                int gn = n0 + tid;
                float m = outs[tid*12];
                #pragma unroll
                for (int l = 1; l < 12; l++) m = fmaxf(m, outs[tid*12 + l]);
                float s = 0.0f, e[12];
                #pragma unroll
                for (int l = 0; l < 12; l++) { e[l] = expf(outs[tid*12 + l] - m); s += e[l]; }
                float inv = 1.0f / s;
                float en = 0.0f;
                #pragma unroll
                for (int l = 0; l < 12; l++) {
                    float p = e[l] * inv;
                    if (gn < NN) g_selL[(size_t)gn*12 + l] = p;
                    en += p * logf(p + 1e-8f);
                }
                ent_s[tid] = (gn < NN) ? en : 0.0f;
            }
            __syncthreads();
        } else {
            if (tid < NPB) {
                int gn = n0 + tid;
                float a = 0.0f;
                for (int k = 0; k < DD; k++) a += h32[tid*H32S + k] * W3c[k];
                float s = 1.0f / (1.0f + expf(-a));
                if (gn < NN) g_ss[gn] = s;
                sq_s[tid] = (gn < NN) ? (s - 0.5f) * (s - 0.5f) : 0.0f;
            }
            __syncthreads();
        }
    }

    if (tid == 0) {
        float es = 0.0f, qs = 0.0f;
        for (int i = 0; i < NPB; i++) { es += ent_s[i]; qs += sq_s[i]; }
        g_part[blockIdx.x*2 + 0] = es;
        g_part[blockIdx.x*2 + 1] = qs;
    }
}

// ---------------- feat GEMM ----------------
__global__ __launch_bounds__(256) void feat_kernel(const float* __restrict__ lt) {
    __shared__ float a_s[8][36];
    __shared__ float w_s[8][128];
    const int lb  = blockIdx.y;
    const int l   = lb >> 2;
    const int hw0 = blockIdx.x * 32;
    const int tid = threadIdx.x;
    const int td  = tid & 31;
    const int thw = tid >> 5;
    const int b   = lb & 3;

    float acc[4][4];
    #pragma unroll
    for (int i = 0; i < 4; i++)
        #pragma unroll
        for (int j = 0; j < 4; j++) acc[i][j] = 0.0f;

    const float* base = lt + (size_t)lb * CC * HWK;

    for (int c0 = 0; c0 < CC; c0 += 8) {
        {
            int kk = tid >> 5, s = tid & 31;
            a_s[kk][s] = base[(size_t)(c0+kk)*HWK + hw0 + s];
            *(float4*)&w_s[kk][s*4] =
                *(const float4*)&g_cwT[((size_t)l*CC + c0 + kk)*DD + s*4];
        }
        __syncthreads();
        #pragma unroll
        for (int kk = 0; kk < 8; kk++) {
            float4 w = *(float4*)&w_s[kk][td*4];
            #pragma unroll
            for (int i = 0; i < 4; i++) {
                float p = a_s[kk][thw*4 + i];
                acc[i][0] += p*w.x; acc[i][1] += p*w.y;
                acc[i][2] += p*w.z; acc[i][3] += p*w.w;
            }
        }
        __syncthreads();
    }
    #pragma unroll
    for (int i = 0; i < 4; i++) {
        int site = hw0 + thw*4 + i;
        float4 v = make_float4(acc[i][0], acc[i][1], acc[i][2], acc[i][3]);
        *(float4*)&g_feat[(((size_t)l*HWK + site)*BB + b)*DD + td*4] = v;
    }
}

// ---------------- global bottleneck ----------------
__global__ __launch_bounds__(256) void gb_kernel(const float* __restrict__ gt,
                                                 const float* __restrict__ gw) {
    int wid  = (blockIdx.x * 256 + threadIdx.x) >> 5;
    int lane = threadIdx.x & 31;
    if (wid >= LL*BB*DD) return;
    int l = wid / (BB*DD);
    int rr = wid - l*(BB*DD);
    int b = rr / DD;
    int d = rr - b*DD;
    const float* a = gt + (size_t)(l*BB + b)*CC;
    const float* w = gw + (size_t)(l*DD + d)*CC;
    float s = 0.0f;
    for (int cc = lane; cc < CC; cc += 32) s += a[cc] * w[cc];
    #pragma unroll
    for (int o = 16; o; o >>= 1) s += __shfl_xor_sync(0xffffffffu, s, o);
    if (lane == 0) g_gb[(size_t)(l*BB + b)*DD + d] = s;
}

// ---------------- binning ----------------
__global__ void init_hist_kernel() {
    int t = blockIdx.x * 256 + threadIdx.x;
    if (t < NCELL) g_hist[t] = 0;
}

__global__ void key_kernel() {
    int n = blockIdx.x * 256 + threadIdx.x;
    if (n >= NN) return;
    int x0 = (int)floorf(g_px[n]);
    int y0 = (int)floorf(g_py[n]);
    x0 = min(max(x0, -1), 15);
    y0 = min(max(y0, -1), 15);
    int key = (y0 + 1) * 17 + (x0 + 1);
    g_key[n] = key;
    atomicAdd(&g_hist[key], 1);
}

__global__ void scan_kernel() {
    if (threadIdx.x != 0 || blockIdx.x != 0) return;
    int off = 0, nch = 0;
    for (int c = 0; c < NCELL; c++) {
        int cnt = g_hist[c];
        g_cur[c] = off;
        for (int base = 0; base < cnt; base += CHUNK) {
            g_chunk_cell[nch] = c;
            g_chunk_base[nch] = off + base;
            g_chunk_cnt [nch] = min(CHUNK, cnt - base);
            nch++;
        }
        off += cnt;
    }
    g_nchunks = nch;
}

__global__ void scatter_kernel() {
    int n = blockIdx.x * 256 + threadIdx.x;
    if (n >= NN) return;
    int pos = atomicAdd(&g_cur[g_key[n]], 1);
    g_perm[pos] = n;
}

// ---------------- final v2: cell-binned gather ----------------
__global__ __launch_bounds__(512) void final2_kernel(const float* __restrict__ ow,
                                                     const float* __restrict__ ob,
                                                     float* __restrict__ out) {
    extern __shared__ float s[];
    float* feat_s = s;                        // [12][4][4][128]
    float* gb_s   = feat_s + 24576;           // [12][4][128]
    float* wL_s   = gb_s + 6144;              // [64][48]
    float* wG_s   = wL_s + 64*48;             // [64][12]
    int*   nidx   = (int*)(wG_s + 64*12);     // [64]

    const int bid = blockIdx.x;
    if (bid >= g_nchunks) return;
    const int tid  = threadIdx.x;
    const int cell = g_chunk_cell[bid];
    const int base = g_chunk_base[bid];
    const int cnt  = g_chunk_cnt [bid];

    const int ky = cell / 17 - 1;
    const int kx = cell % 17 - 1;
    const bool vx0 = (kx >= 0),  vx1 = (kx + 1 <= 15);
    const bool vy0 = (ky >= 0),  vy1 = (ky + 1 <= 15);
    const int sx0 = min(max(kx,     0), 15), sx1 = min(max(kx + 1, 0), 15);
    const int sy0 = min(max(ky,     0), 15), sy1 = min(max(ky + 1, 0), 15);
    int site[4];
    site[0] = sy0*16 + sx0; site[1] = sy0*16 + sx1;
    site[2] = sy1*16 + sx0; site[3] = sy1*16 + sx1;

    {
        const float4* gf = (const float4*)g_feat;
        float4* fs = (float4*)feat_s;
        #pragma unroll
        for (int it = 0; it < 12; it++) {
            int i = tid + it*512;
            int l  = i >> 9;
            int rm = i & 511;
            int p  = rm >> 7;
            int b  = (rm >> 5) & 3;
            int d4 = rm & 31;
            fs[i] = gf[((l*HWK + site[p])*BB + b)*32 + d4];
        }
        const float4* gg = (const float4*)g_gb;
        float4* gs = (float4*)gb_s;
        #pragma unroll
        for (int it = 0; it < 3; it++)
            gs[tid + it*512] = gg[tid + it*512];
    }

    if (tid < CHUNK) {
        int n = (tid < cnt) ? g_perm[base + tid] : -1;
        nidx[tid] = n;
        if (n >= 0) {
            float px = g_px[n], py = g_py[n], ss = g_ss[n];
            float wx1 = px - (float)kx, wy1 = py - (float)ky;
            float wx0 = 1.0f - wx1, wy0 = 1.0f - wy1;
            float cw[4];
            cw[0] = (vx0 && vy0) ? wx0*wy0 : 0.0f;
            cw[1] = (vx1 && vy0) ? wx1*wy0 : 0.0f;
            cw[2] = (vx0 && vy1) ? wx0*wy1 : 0.0f;
            cw[3] = (vx1 && vy1) ? wx1*wy1 : 0.0f;
            float oms = 1.0f - ss;
            #pragma unroll
            for (int l = 0; l < LL; l++) {
                float wl = g_selL[(size_t)n*12 + l];
                float owl = oms * wl;
                wL_s[tid*48 + l*4 + 0] = owl * cw[0];
                wL_s[tid*48 + l*4 + 1] = owl * cw[1];
                wL_s[tid*48 + l*4 + 2] = owl * cw[2];
                wL_s[tid*48 + l*4 + 3] = owl * cw[3];
                wG_s[tid*12 + l] = ss * wl;
            }
        } else {
            #pragma unroll
            for (int l = 0; l < LL; l++) {
                wL_s[tid*48 + l*4 + 0] = 0.0f; wL_s[tid*48 + l*4 + 1] = 0.0f;
                wL_s[tid*48 + l*4 + 2] = 0.0f; wL_s[tid*48 + l*4 + 3] = 0.0f;
                wG_s[tid*12 + l] = 0.0f;
            }
        }
    }
    __syncthreads();

    const int wid  = tid >> 5;
    const int lane = tid & 31;
    const int b    = wid & 3;
    const int pg   = wid >> 2;
    const float4* fs = (const float4*)feat_s;
    const float4* gs = (const float4*)gb_s;
    const float*  wLp = wL_s + (pg*16)*48;
    const float*  wGp = wG_s + (pg*16)*12;

    float4 acc[16];
    #pragma unroll
    for (int k = 0; k < 16; k++) acc[k] = make_float4(0,0,0,0);

    for (int l = 0; l < LL; l++) {
        #pragma unroll
        for (int p = 0; p < 4; p++) {
            float4 f = fs[(l*16 + p*4 + b)*32 + lane];
            #pragma unroll
            for (int k = 0; k < 16; k++) {
                float w = wLp[k*48 + l*4 + p];
                acc[k].x += w*f.x; acc[k].y += w*f.y;
                acc[k].z += w*f.z; acc[k].w += w*f.w;
            }
        }
        float4 g = gs[(l*4 + b)*32 + lane];
        #pragma unroll
        for (int k = 0; k < 16; k++) {
            float w = wGp[k*12 + l];
            acc[k].x += w*g.x; acc[k].y += w*g.y;
            acc[k].z += w*g.z; acc[k].w += w*g.w;
        }
    }

    #pragma unroll
    for (int k = 0; k < 16; k++) {
        int n = nidx[pg*16 + k];
        if (n < 0) continue;
        float4 o4 = *(const float4*)&ow[(size_t)n*DD + lane*4];
        float dot = acc[k].x*o4.x + acc[k].y*o4.y + acc[k].z*o4.z + acc[k].w*o4.w;
        #pragma unroll
        for (int o = 16; o; o >>= 1) dot += __shfl_xor_sync(0xffffffffu, dot, o);
        if (lane == 0) out[b*NN + n] = dot * (1.0f/DD) + ob[n];
    }
}

// ---------------- reg scalar ----------------
__global__ void reg_kernel(float* __restrict__ out, int has_reg) {
    if (threadIdx.x == 0 && blockIdx.x == 0) {
        float es = 0.0f, qs = 0.0f;
        for (int i = 0; i < NBLK_SEL; i++) { es += g_part[2*i]; qs += g_part[2*i+1]; }
        float entropy = es / (float)NN;
        float reg = entropy / logf(12.0f) + qs / (float)NN;
        if (has_reg) out[BB*NN] = reg;
    }
}

// ---------------- launch ----------------
extern "C" void kernel_launch(void* const* d_in, const int* in_sizes, int n_in,
                              void* d_out, int out_size) {
    const float* lt     = (const float*)d_in[0];
    const float* gt     = (const float*)d_in[1];
    const float* coords = (const float*)d_in[2];
    const float* conv_w = (const float*)d_in[3];
    const float* glob_w = (const float*)d_in[4];
    const float* W1     = (const float*)d_in[5];
    const float* b1     = (const float*)d_in[6];
    const float* W2     = (const float*)d_in[7];
    const float* b2     = (const float*)d_in[8];
    const float* W3s    = (const float*)d_in[9];
    const float* W3l    = (const float*)d_in[10];
    const float* W3c    = (const float*)d_in[11];
    const float* ow     = (const float*)d_in[12];
    const float* ob     = (const float*)d_in[13];
    float* out = (float*)d_out;

    cudaFuncSetAttribute(selector3_kernel,
                         cudaFuncAttributeMaxDynamicSharedMemorySize, SEL_SMEM_BYTES);
    cudaFuncSetAttribute(final2_kernel,
                         cudaFuncAttributeMaxDynamicSharedMemorySize, FIN_SMEM_BYTES);

    // order chosen so selector3 is the 4th launch (ncu capture slot)
    wpack_kernel<<<(3*96*128 + 3*64*128 + 255)/256, 256>>>(W1, W2);
    transpose_cw_kernel<<<dim3(4, 24, 12), dim3(32, 8)>>>(conv_w);
    feat_kernel<<<dim3(8, 48), 256>>>(lt);
    selector3_kernel<<<NBLK_SEL, 256, SEL_SMEM_BYTES>>>(coords, b1, b2, W3s, W3l, W3c);
    gb_kernel<<<768, 256>>>(gt, glob_w);
    init_hist_kernel<<<2, 256>>>();
    key_kernel<<<(NN + 255)/256, 256>>>();
    scan_kernel<<<1, 32>>>();
    scatter_kernel<<<(NN + 255)/256, 256>>>();
    final2_kernel<<<NCHUNK_MAX, 512, FIN_SMEM_BYTES>>>(ow, ob, out);
    reg_kernel<<<1, 32>>>(out, (out_size > BB*NN) ? 1 : 0);
}

// round 9
// speedup vs baseline: 1.3619x; 1.1571x over previous
#include <cuda_runtime.h>
#include <cuda_bf16.h>
#include <cstdint>
#include <math.h>

#define LL   12
#define BB   4
#define CC   768
#define HHH  16
#define WWW  16
#define NN   30000
#define DD   128
#define PEK  192
#define HWK  256
#define NPB  64
#define NBLK_SEL 469               // ceil(30000/64)

#define NCELL 289                  // 17*17 bilinear cells
#define CHUNK 64
#define NCHUNK_MAX (NCELL + (NN + CHUNK - 1) / CHUNK)   // 758

// packed-pair strides (uint32 words); ≡4 (mod 32) for conflict-free frags
#define PE2S 100                   // 96 pairs + pad
#define H2S  68                    // 64 pairs + pad
#define W2S  132                   // 128 j + pad
#define WCH  16                    // staged k-pairs per chunk (32 K)

// selector smem words: pe(2*6400) + hp(2*4352) + w(2*WCH*W2S=4224) + outs(768) + 128
#define SEL_SMEM_WORDS (2*NPB*PE2S + 2*NPB*H2S + 2*WCH*W2S + NPB*12 + 2*NPB)
#define SEL_SMEM_BYTES (SEL_SMEM_WORDS * 4)     // 106496 -> 2 blocks/SM

#define FIN_SMEM_BYTES (98304 + 24576 + 12288 + 3072 + 256)

// ---------------- scratch ----------------
__device__ float g_cwT [LL*CC*DD];
__device__ float g_feat[LL*HWK*BB*DD];    // [l][site][b][d]
__device__ float g_gb  [LL*BB*DD];
__device__ float g_selL[NN*LL];
__device__ float g_px  [NN];
__device__ float g_py  [NN];
__device__ float g_ss  [NN];
__device__ float g_part[2*NBLK_SEL];
// packed bf16x2 weights (hi/lo split), pair-major [mat][kp][j]
__device__ unsigned int g_w1h[3*96*128];
__device__ unsigned int g_w1l[3*96*128];
__device__ unsigned int g_w2h[3*64*128];
__device__ unsigned int g_w2l[3*64*128];
// binning
__device__ int g_key [NN];
__device__ int g_perm[NN];
__device__ int g_hist[NCELL];
__device__ int g_cur [NCELL];
__device__ int g_chunk_cell[NCHUNK_MAX];
__device__ int g_chunk_base[NCHUNK_MAX];
__device__ int g_chunk_cnt [NCHUNK_MAX];
__device__ int g_nchunks;

__device__ __forceinline__ float gelu_exact(float x) {
    return 0.5f * x * (1.0f + erff(x * 0.7071067811865476f));
}

__device__ __forceinline__ unsigned int pack_hi(float v0, float v1) {
    unsigned short u0 = __bfloat16_as_ushort(__float2bfloat16_rn(v0));
    unsigned short u1 = __bfloat16_as_ushort(__float2bfloat16_rn(v1));
    return (unsigned int)u0 | ((unsigned int)u1 << 16);
}
__device__ __forceinline__ unsigned int pack_lo(float v0, float v1) {
    float h0 = __bfloat162float(__float2bfloat16_rn(v0));
    float h1 = __bfloat162float(__float2bfloat16_rn(v1));
    unsigned short u0 = __bfloat16_as_ushort(__float2bfloat16_rn(v0 - h0));
    unsigned short u1 = __bfloat16_as_ushort(__float2bfloat16_rn(v1 - h1));
    return (unsigned int)u0 | ((unsigned int)u1 << 16);
}
// unpack hi+lo packed pairs to two fp32 values
__device__ __forceinline__ float2 unpack_hl(unsigned int hi, unsigned int lo) {
    __nv_bfloat162 h = *reinterpret_cast<__nv_bfloat162*>(&hi);
    __nv_bfloat162 l = *reinterpret_cast<__nv_bfloat162*>(&lo);
    float2 r;
    r.x = __bfloat162float(h.x) + __bfloat162float(l.x);
    r.y = __bfloat162float(h.y) + __bfloat162float(l.y);
    return r;
}

__device__ __forceinline__ void mma_bf16(float c[4],
    unsigned int a0, unsigned int a1, unsigned int a2, unsigned int a3,
    unsigned int b0, unsigned int b1) {
    asm volatile(
        "mma.sync.aligned.m16n8k16.row.col.f32.bf16.bf16.f32 "
        "{%0,%1,%2,%3},{%4,%5,%6,%7},{%8,%9},{%0,%1,%2,%3};\n"
        : "+f"(c[0]), "+f"(c[1]), "+f"(c[2]), "+f"(c[3])
        : "r"(a0), "r"(a1), "r"(a2), "r"(a3), "r"(b0), "r"(b1));
}

// ---------------- weight pack: fp32 [k][j] -> bf16x2 hi/lo [k/2][j] ----------------
__global__ void wpack_kernel(const float* __restrict__ W1all,
                             const float* __restrict__ W2all) {
    int i = blockIdx.x * 256 + threadIdx.x;
    if (i < 3*96*128) {
        int mat = i / (96*128);
        int rem = i - mat*(96*128);
        int kp = rem >> 7, j = rem & 127;
        const float* W = W1all + (size_t)mat*PEK*DD;
        float w0 = W[(2*kp)*DD + j], w1 = W[(2*kp+1)*DD + j];
        g_w1h[i] = pack_hi(w0, w1);
        g_w1l[i] = pack_lo(w0, w1);
    } else if (i < 3*96*128 + 3*64*128) {
        int t = i - 3*96*128;
        int mat = t / (64*128);
        int rem = t - mat*(64*128);
        int kp = rem >> 7, j = rem & 127;
        const float* W = W2all + (size_t)mat*DD*DD;
        float w0 = W[(2*kp)*DD + j], w1 = W[(2*kp+1)*DD + j];
        g_w2h[t] = pack_hi(w0, w1);
        g_w2l[t] = pack_lo(w0, w1);
    }
}

// ---------------- conv_w transpose ----------------
__global__ void transpose_cw_kernel(const float* __restrict__ cw) {
    __shared__ float t[32][33];
    const int l  = blockIdx.z;
    const int d0 = blockIdx.x * 32;
    const int c0 = blockIdx.y * 32;
    for (int i = threadIdx.y; i < 32; i += 8)
        t[i][threadIdx.x] = cw[((size_t)l*DD + d0 + i)*CC + c0 + threadIdx.x];
    __syncthreads();
    for (int i = threadIdx.y; i < 32; i += 8)
        g_cwT[((size_t)l*CC + c0 + i)*DD + d0 + threadIdx.x] = t[threadIdx.x][i];
}

// ---------------- selector v5: 3xBF16 MLP, 2 blocks/SM ----------------
__device__ __forceinline__ void gemm_layer_3xbf16(
    const unsigned int* Aph, const unsigned int* Apl, int A2S, int KP,
    const unsigned int* __restrict__ Wgh, const unsigned int* __restrict__ Wgl,
    unsigned int* wh_s, unsigned int* wl_s, float cacc[8][4],
    int tid, int nw, int jw, int gid, int tig)
{
    for (int kc2 = 0; kc2 < KP; kc2 += WCH) {   // 16 pairs = 32 K per chunk
        __syncthreads();
        for (int i = tid; i < WCH*32; i += 256) {
            int row = i >> 5, c4 = (i & 31) * 4;
            *(uint4*)&wh_s[row*W2S + c4] = *(const uint4*)&Wgh[(kc2+row)*128 + c4];
            *(uint4*)&wl_s[row*W2S + c4] = *(const uint4*)&Wgl[(kc2+row)*128 + c4];
        }
        __syncthreads();
        #pragma unroll
        for (int s = 0; s < 2; s++) {          // 2 k16 steps per chunk
            int kpA = kc2 + s*8;
            unsigned int ah0 = Aph[(nw+gid  )*A2S + kpA + tig];
            unsigned int ah1 = Aph[(nw+gid+8)*A2S + kpA + tig];
            unsigned int ah2 = Aph[(nw+gid  )*A2S + kpA + tig + 4];
            unsigned int ah3 = Aph[(nw+gid+8)*A2S + kpA + tig + 4];
            unsigned int al0 = Apl[(nw+gid  )*A2S + kpA + tig];
            unsigned int al1 = Apl[(nw+gid+8)*A2S + kpA + tig];
            unsigned int al2 = Apl[(nw+gid  )*A2S + kpA + tig + 4];
            unsigned int al3 = Apl[(nw+gid+8)*A2S + kpA + tig + 4];
            int kps = s*8;
            #pragma unroll
            for (int jt = 0; jt < 8; jt++) {
                int j = jw + jt*8 + gid;
                unsigned int bh0 = wh_s[(kps+tig  )*W2S + j];
                unsigned int bh1 = wh_s[(kps+tig+4)*W2S + j];
                unsigned int bl0 = wl_s[(kps+tig  )*W2S + j];
                unsigned int bl1 = wl_s[(kps+tig+4)*W2S + j];
                mma_bf16(cacc[jt], ah0, ah1, ah2, ah3, bh0, bh1);
                mma_bf16(cacc[jt], al0, al1, al2, al3, bh0, bh1);
                mma_bf16(cacc[jt], ah0, ah1, ah2, ah3, bl0, bl1);
            }
        }
    }
}

__global__ __launch_bounds__(256) void selector3_kernel(
    const float* __restrict__ coords,
    const float* __restrict__ b1all, const float* __restrict__ b2all,
    const float* __restrict__ W3s,   const float* __restrict__ W3l,
    const float* __restrict__ W3c)
{
    extern __shared__ unsigned int smem_u[];
    unsigned int* pe_h = smem_u;                 // [64][PE2S]
    unsigned int* pe_l = pe_h + NPB*PE2S;
    unsigned int* h_ph = pe_l + NPB*PE2S;        // [64][H2S] (holds h1, then h2)
    unsigned int* h_pl = h_ph + NPB*H2S;
    unsigned int* wh_s = h_pl + NPB*H2S;         // [WCH][W2S]
    unsigned int* wl_s = wh_s + WCH*W2S;
    float* outs  = (float*)(wl_s + WCH*W2S);     // [64][12]
    float* ent_s = outs + NPB*12;
    float* sq_s  = ent_s + NPB;

    const int tid  = threadIdx.x;
    const int n0   = blockIdx.x * NPB;
    const int wid  = tid >> 5;
    const int lane = tid & 31;
    const int gid  = lane >> 2;
    const int tig  = lane & 3;
    const int nw   = (wid >> 1) * 16;
    const int jw   = (wid & 1) * 64;

    for (int idx = tid; idx < NPB*96; idx += 256) {
        int n = idx / 96, kp = idx - n*96;
        int gn = n0 + n;
        float v[2];
        #pragma unroll
        for (int e = 0; e < 2; e++) {
            int k = 2*kp + e;
            int cc = k >> 6, rr = k & 63, f = rr & 31;
            float x = (gn < NN) ? coords[gn*3 + cc] : 0.0f;
            float freq = exp2f((8.0f/31.0f) * (float)f) * 3.14159265358979323846f;
            float ang = x * freq;
            v[e] = (rr < 32) ? sinf(ang) : cosf(ang);
        }
        pe_h[n*PE2S + kp] = pack_hi(v[0], v[1]);
        pe_l[n*PE2S + kp] = pack_lo(v[0], v[1]);
    }
    __syncthreads();

    for (int head = 0; head < 3; head++) {
        float cacc[8][4];

        // ---- layer 1: h1 = gelu(pe @ W1 + b1) -> packed hi/lo into h_p
        #pragma unroll
        for (int jt = 0; jt < 8; jt++)
            #pragma unroll
            for (int i = 0; i < 4; i++) cacc[jt][i] = 0.0f;
        gemm_layer_3xbf16(pe_h, pe_l, PE2S, 96,
                          g_w1h + head*96*128, g_w1l + head*96*128,
                          wh_s, wl_s, cacc, tid, nw, jw, gid, tig);
        __syncthreads();   // h_p (h2 of prev head) last read in W3 stage; also orders below writes
        #pragma unroll
        for (int jt = 0; jt < 8; jt++) {
            int col = jw + jt*8 + 2*tig;
            int kp  = col >> 1;
            float bz0 = b1all[head*DD + col], bz1 = b1all[head*DD + col + 1];
            float v0 = gelu_exact(cacc[jt][0] + bz0);
            float v1 = gelu_exact(cacc[jt][1] + bz1);
            float v2 = gelu_exact(cacc[jt][2] + bz0);
            float v3 = gelu_exact(cacc[jt][3] + bz1);
            h_ph[(nw+gid  )*H2S + kp] = pack_hi(v0, v1);
            h_pl[(nw+gid  )*H2S + kp] = pack_lo(v0, v1);
            h_ph[(nw+gid+8)*H2S + kp] = pack_hi(v2, v3);
            h_pl[(nw+gid+8)*H2S + kp] = pack_lo(v2, v3);
        }
        // ---- layer 2: h2 = gelu(h1 @ W2 + b2) -> packed hi/lo back into h_p
        #pragma unroll
        for (int jt = 0; jt < 8; jt++)
            #pragma unroll
            for (int i = 0; i < 4; i++) cacc[jt][i] = 0.0f;
        gemm_layer_3xbf16(h_ph, h_pl, H2S, 64,
                          g_w2h + head*64*128, g_w2l + head*64*128,
                          wh_s, wl_s, cacc, tid, nw, jw, gid, tig);
        __syncthreads();   // all mma reads of h1 done before overwrite
        #pragma unroll
        for (int jt = 0; jt < 8; jt++) {
            int col = jw + jt*8 + 2*tig;
            int kp  = col >> 1;
            float bz0 = b2all[head*DD + col], bz1 = b2all[head*DD + col + 1];
            float v0 = gelu_exact(cacc[jt][0] + bz0);
            float v1 = gelu_exact(cacc[jt][1] + bz1);
            float v2 = gelu_exact(cacc[jt][2] + bz0);
            float v3 = gelu_exact(cacc[jt][3] + bz1);
            h_ph[(nw+gid  )*H2S + kp] = pack_hi(v0, v1);
            h_pl[(nw+gid  )*H2S + kp] = pack_lo(v0, v1);
            h_ph[(nw+gid+8)*H2S + kp] = pack_hi(v2, v3);
            h_pl[(nw+gid+8)*H2S + kp] = pack_lo(v2, v3);
        }
        __syncthreads();

        // ---- W3 + activation (fp32 scalar; h2 unpacked hi+lo)
        if (head == 0) {
            if (tid < 128) {
                int n = tid >> 1, j = tid & 1;
                float a = 0.0f;
                for (int kp = 0; kp < 64; kp++) {
                    float2 h = unpack_hl(h_ph[n*H2S + kp], h_pl[n*H2S + kp]);
                    a += h.x * W3s[(2*kp)*2 + j] + h.y * W3s[(2*kp+1)*2 + j];
                }
                outs[n*12 + j] = tanhf(a);
            }
            __syncthreads();
            if (tid < NPB) {
                int gn = n0 + tid;
                if (gn < NN) {
                    g_px[gn] = (outs[tid*12 + 0] + 1.0f) * (WWW * 0.5f) - 0.5f;
                    g_py[gn] = (outs[tid*12 + 1] + 1.0f) * (HHH * 0.5f) - 0.5f;
                }
            }
            __syncthreads();
        } else if (head == 1) {
            for (int idx = tid; idx < NPB*12; idx += 256) {
                int n = idx / 12, j = idx - n*12;
                float a = 0.0f;
                for (int kp = 0; kp < 64; kp++) {
                    float2 h = unpack_hl(h_ph[n*H2S + kp], h_pl[n*H2S + kp]);
                    a += h.x * W3l[(2*kp)*12 + j] + h.y * W3l[(2*kp+1)*12 + j];
                }
                outs[n*12 + j] = a;
            }
            __syncthreads();
            if (tid < NPB) {
                int gn = n0 + tid;
                float m = outs[tid*12];
                #pragma unroll
                for (int l = 1; l < 12; l++) m = fmaxf(m, outs[tid*12 + l]);
                float s = 0.0f, e[12];
                #pragma unroll
                for (int l = 0; l < 12; l++) { e[l] = expf(outs[tid*12 + l] - m); s += e[l]; }
                float inv = 1.0f / s;
                float en = 0.0f;
                #pragma unroll
                for (int l = 0; l < 12; l++) {
                    float p = e[l] * inv;
                    if (gn < NN) g_selL[(size_t)gn*12 + l] = p;
                    en += p * logf(p + 1e-8f);
                }
                ent_s[tid] = (gn < NN) ? en : 0.0f;
            }
            __syncthreads();
        } else {
            if (tid < NPB) {
                int gn = n0 + tid;
                float a = 0.0f;
                for (int kp = 0; kp < 64; kp++) {
                    float2 h = unpack_hl(h_ph[tid*H2S + kp], h_pl[tid*H2S + kp]);
                    a += h.x * W3c[2*kp] + h.y * W3c[2*kp+1];
                }
                float s = 1.0f / (1.0f + expf(-a));
                if (gn < NN) g_ss[gn] = s;
                sq_s[tid] = (gn < NN) ? (s - 0.5f) * (s - 0.5f) : 0.0f;
            }
            __syncthreads();
        }
    }

    if (tid == 0) {
        float es = 0.0f, qs = 0.0f;
        for (int i = 0; i < NPB; i++) { es += ent_s[i]; qs += sq_s[i]; }
        g_part[blockIdx.x*2 + 0] = es;
        g_part[blockIdx.x*2 + 1] = qs;
    }
}

// ---------------- feat GEMM ----------------
__global__ __launch_bounds__(256) void feat_kernel(const float* __restrict__ lt) {
    __shared__ float a_s[8][36];
    __shared__ float w_s[8][128];
    const int lb  = blockIdx.y;
    const int l   = lb >> 2;
    const int hw0 = blockIdx.x * 32;
    const int tid = threadIdx.x;
    const int td  = tid & 31;
    const int thw = tid >> 5;
    const int b   = lb & 3;

    float acc[4][4];
    #pragma unroll
    for (int i = 0; i < 4; i++)
        #pragma unroll
        for (int j = 0; j < 4; j++) acc[i][j] = 0.0f;

    const float* base = lt + (size_t)lb * CC * HWK;

    for (int c0 = 0; c0 < CC; c0 += 8) {
        {
            int kk = tid >> 5, s = tid & 31;
            a_s[kk][s] = base[(size_t)(c0+kk)*HWK + hw0 + s];
            *(float4*)&w_s[kk][s*4] =
                *(const float4*)&g_cwT[((size_t)l*CC + c0 + kk)*DD + s*4];
        }
        __syncthreads();
        #pragma unroll
        for (int kk = 0; kk < 8; kk++) {
            float4 w = *(float4*)&w_s[kk][td*4];
            #pragma unroll
            for (int i = 0; i < 4; i++) {
                float p = a_s[kk][thw*4 + i];
                acc[i][0] += p*w.x; acc[i][1] += p*w.y;
                acc[i][2] += p*w.z; acc[i][3] += p*w.w;
            }
        }
        __syncthreads();
    }
    #pragma unroll
    for (int i = 0; i < 4; i++) {
        int site = hw0 + thw*4 + i;
        float4 v = make_float4(acc[i][0], acc[i][1], acc[i][2], acc[i][3]);
        *(float4*)&g_feat[(((size_t)l*HWK + site)*BB + b)*DD + td*4] = v;
    }
}

// ---------------- global bottleneck ----------------
__global__ __launch_bounds__(256) void gb_kernel(const float* __restrict__ gt,
                                                 const float* __restrict__ gw) {
    int wid  = (blockIdx.x * 256 + threadIdx.x) >> 5;
    int lane = threadIdx.x & 31;
    if (wid >= LL*BB*DD) return;
    int l = wid / (BB*DD);
    int rr = wid - l*(BB*DD);
    int b = rr / DD;
    int d = rr - b*DD;
    const float* a = gt + (size_t)(l*BB + b)*CC;
    const float* w = gw + (size_t)(l*DD + d)*CC;
    float s = 0.0f;
    for (int cc = lane; cc < CC; cc += 32) s += a[cc] * w[cc];
    #pragma unroll
    for (int o = 16; o; o >>= 1) s += __shfl_xor_sync(0xffffffffu, s, o);
    if (lane == 0) g_gb[(size_t)(l*BB + b)*DD + d] = s;
}

// ---------------- binning ----------------
__global__ void init_hist_kernel() {
    int t = blockIdx.x * 256 + threadIdx.x;
    if (t < NCELL) g_hist[t] = 0;
}

__global__ void key_kernel() {
    int n = blockIdx.x * 256 + threadIdx.x;
    if (n >= NN) return;
    int x0 = (int)floorf(g_px[n]);
    int y0 = (int)floorf(g_py[n]);
    x0 = min(max(x0, -1), 15);
    y0 = min(max(y0, -1), 15);
    int key = (y0 + 1) * 17 + (x0 + 1);
    g_key[n] = key;
    atomicAdd(&g_hist[key], 1);
}

__global__ void scan_kernel() {
    if (threadIdx.x != 0 || blockIdx.x != 0) return;
    int off = 0, nch = 0;
    for (int c = 0; c < NCELL; c++) {
        int cnt = g_hist[c];
        g_cur[c] = off;
        for (int base = 0; base < cnt; base += CHUNK) {
            g_chunk_cell[nch] = c;
            g_chunk_base[nch] = off + base;
            g_chunk_cnt [nch] = min(CHUNK, cnt - base);
            nch++;
        }
        off += cnt;
    }
    g_nchunks = nch;
}

__global__ void scatter_kernel() {
    int n = blockIdx.x * 256 + threadIdx.x;
    if (n >= NN) return;
    int pos = atomicAdd(&g_cur[g_key[n]], 1);
    g_perm[pos] = n;
}

// ---------------- final v2: cell-binned gather ----------------
__global__ __launch_bounds__(512) void final2_kernel(const float* __restrict__ ow,
                                                     const float* __restrict__ ob,
                                                     float* __restrict__ out) {
    extern __shared__ float s[];
    float* feat_s = s;                        // [12][4][4][128]
    float* gb_s   = feat_s + 24576;           // [12][4][128]
    float* wL_s   = gb_s + 6144;              // [64][48]
    float* wG_s   = wL_s + 64*48;             // [64][12]
    int*   nidx   = (int*)(wG_s + 64*12);     // [64]

    const int bid = blockIdx.x;
    if (bid >= g_nchunks) return;
    const int tid  = threadIdx.x;
    const int cell = g_chunk_cell[bid];
    const int base = g_chunk_base[bid];
    const int cnt  = g_chunk_cnt [bid];

    const int ky = cell / 17 - 1;
    const int kx = cell % 17 - 1;
    const bool vx0 = (kx >= 0),  vx1 = (kx + 1 <= 15);
    const bool vy0 = (ky >= 0),  vy1 = (ky + 1 <= 15);
    const int sx0 = min(max(kx,     0), 15), sx1 = min(max(kx + 1, 0), 15);
    const int sy0 = min(max(ky,     0), 15), sy1 = min(max(ky + 1, 0), 15);
    int site[4];
    site[0] = sy0*16 + sx0; site[1] = sy0*16 + sx1;
    site[2] = sy1*16 + sx0; site[3] = sy1*16 + sx1;

    {
        const float4* gf = (const float4*)g_feat;
        float4* fs = (float4*)feat_s;
        #pragma unroll
        for (int it = 0; it < 12; it++) {
            int i = tid + it*512;
            int l  = i >> 9;
            int rm = i & 511;
            int p  = rm >> 7;
            int b  = (rm >> 5) & 3;
            int d4 = rm & 31;
            fs[i] = gf[((l*HWK + site[p])*BB + b)*32 + d4];
        }
        const float4* gg = (const float4*)g_gb;
        float4* gs = (float4*)gb_s;
        #pragma unroll
        for (int it = 0; it < 3; it++)
            gs[tid + it*512] = gg[tid + it*512];
    }

    if (tid < CHUNK) {
        int n = (tid < cnt) ? g_perm[base + tid] : -1;
        nidx[tid] = n;
        if (n >= 0) {
            float px = g_px[n], py = g_py[n], ss = g_ss[n];
            float wx1 = px - (float)kx, wy1 = py - (float)ky;
            float wx0 = 1.0f - wx1, wy0 = 1.0f - wy1;
            float cw[4];
            cw[0] = (vx0 && vy0) ? wx0*wy0 : 0.0f;
            cw[1] = (vx1 && vy0) ? wx1*wy0 : 0.0f;
            cw[2] = (vx0 && vy1) ? wx0*wy1 : 0.0f;
            cw[3] = (vx1 && vy1) ? wx1*wy1 : 0.0f;
            float oms = 1.0f - ss;
            #pragma unroll
            for (int l = 0; l < LL; l++) {
                float wl = g_selL[(size_t)n*12 + l];
                float owl = oms * wl;
                wL_s[tid*48 + l*4 + 0] = owl * cw[0];
                wL_s[tid*48 + l*4 + 1] = owl * cw[1];
                wL_s[tid*48 + l*4 + 2] = owl * cw[2];
                wL_s[tid*48 + l*4 + 3] = owl * cw[3];
                wG_s[tid*12 + l] = ss * wl;
            }
        } else {
            #pragma unroll
            for (int l = 0; l < LL; l++) {
                wL_s[tid*48 + l*4 + 0] = 0.0f; wL_s[tid*48 + l*4 + 1] = 0.0f;
                wL_s[tid*48 + l*4 + 2] = 0.0f; wL_s[tid*48 + l*4 + 3] = 0.0f;
                wG_s[tid*12 + l] = 0.0f;
            }
        }
    }
    __syncthreads();

    const int wid  = tid >> 5;
    const int lane = tid & 31;
    const int b    = wid & 3;
    const int pg   = wid >> 2;
    const float4* fs = (const float4*)feat_s;
    const float4* gs = (const float4*)gb_s;
    const float*  wLp = wL_s + (pg*16)*48;
    const float*  wGp = wG_s + (pg*16)*12;

    float4 acc[16];
    #pragma unroll
    for (int k = 0; k < 16; k++) acc[k] = make_float4(0,0,0,0);

    for (int l = 0; l < LL; l++) {
        #pragma unroll
        for (int p = 0; p < 4; p++) {
            float4 f = fs[(l*16 + p*4 + b)*32 + lane];
            #pragma unroll
            for (int k = 0; k < 16; k++) {
                float w = wLp[k*48 + l*4 + p];
                acc[k].x += w*f.x; acc[k].y += w*f.y;
                acc[k].z += w*f.z; acc[k].w += w*f.w;
            }
        }
        float4 g = gs[(l*4 + b)*32 + lane];
        #pragma unroll
        for (int k = 0; k < 16; k++) {
            float w = wGp[k*12 + l];
            acc[k].x += w*g.x; acc[k].y += w*g.y;
            acc[k].z += w*g.z; acc[k].w += w*g.w;
        }
    }

    #pragma unroll
    for (int k = 0; k < 16; k++) {
        int n = nidx[pg*16 + k];
        if (n < 0) continue;
        float4 o4 = *(const float4*)&ow[(size_t)n*DD + lane*4];
        float dot = acc[k].x*o4.x + acc[k].y*o4.y + acc[k].z*o4.z + acc[k].w*o4.w;
        #pragma unroll
        for (int o = 16; o; o >>= 1) dot += __shfl_xor_sync(0xffffffffu, dot, o);
        if (lane == 0) out[b*NN + n] = dot * (1.0f/DD) + ob[n];
    }
}

// ---------------- reg scalar ----------------
__global__ void reg_kernel(float* __restrict__ out, int has_reg) {
    if (threadIdx.x == 0 && blockIdx.x == 0) {
        float es = 0.0f, qs = 0.0f;
        for (int i = 0; i < NBLK_SEL; i++) { es += g_part[2*i]; qs += g_part[2*i+1]; }
        float entropy = es / (float)NN;
        float reg = entropy / logf(12.0f) + qs / (float)NN;
        if (has_reg) out[BB*NN] = reg;
    }
}

// ---------------- launch ----------------
extern "C" void kernel_launch(void* const* d_in, const int* in_sizes, int n_in,
                              void* d_out, int out_size) {
    const float* lt     = (const float*)d_in[0];
    const float* gt     = (const float*)d_in[1];
    const float* coords = (const float*)d_in[2];
    const float* conv_w = (const float*)d_in[3];
    const float* glob_w = (const float*)d_in[4];
    const float* W1     = (const float*)d_in[5];
    const float* b1     = (const float*)d_in[6];
    const float* W2     = (const float*)d_in[7];
    const float* b2     = (const float*)d_in[8];
    const float* W3s    = (const float*)d_in[9];
    const float* W3l    = (const float*)d_in[10];
    const float* W3c    = (const float*)d_in[11];
    const float* ow     = (const float*)d_in[12];
    const float* ob     = (const float*)d_in[13];
    float* out = (float*)d_out;

    cudaFuncSetAttribute(selector3_kernel,
                         cudaFuncAttributeMaxDynamicSharedMemorySize, SEL_SMEM_BYTES);
    cudaFuncSetAttribute(final2_kernel,
                         cudaFuncAttributeMaxDynamicSharedMemorySize, FIN_SMEM_BYTES);

    // order chosen so selector3 is the 4th launch (ncu capture slot)
    wpack_kernel<<<(3*96*128 + 3*64*128 + 255)/256, 256>>>(W1, W2);
    transpose_cw_kernel<<<dim3(4, 24, 12), dim3(32, 8)>>>(conv_w);
    feat_kernel<<<dim3(8, 48), 256>>>(lt);
    selector3_kernel<<<NBLK_SEL, 256, SEL_SMEM_BYTES>>>(coords, b1, b2, W3s, W3l, W3c);
    gb_kernel<<<768, 256>>>(gt, glob_w);
    init_hist_kernel<<<2, 256>>>();
    key_kernel<<<(NN + 255)/256, 256>>>();
    scan_kernel<<<1, 32>>>();
    scatter_kernel<<<(NN + 255)/256, 256>>>();
    final2_kernel<<<NCHUNK_MAX, 512, FIN_SMEM_BYTES>>>(ow, ob, out);
    reg_kernel<<<1, 32>>>(out, (out_size > BB*NN) ? 1 : 0);
}